// round 15
// baseline (speedup 1.0000x reference)
#include <cuda_runtime.h>
#include <cuda_fp16.h>
#include <cstdint>
#include <cstddef>

#define N_NODES 100000
#define N_EDGES 1600000

// ---------------- scratch ----------------
// g_NPh interleaved layout per node (256 halfs):
//   [0:128)   src part : for q in 0..15: halves 8q..8q+3 = f cols 4q..4q+3,
//                                         halves 8q+4..8q+7 = s cols 4q..4q+3
//   [128:256) tgt part : same structure
__device__ __align__(16) __half g_NPh[(size_t)N_NODES * 256];
__device__ __align__(16) float g_msg[(size_t)N_NODES * 64];
__device__ __align__(16) unsigned int g_Bh[128 * 16];   // permuted fp16 edge-B tile
__device__ __align__(16) unsigned int g_Bn[256 * 32];   // permuted fp16 node-W tile
__device__ double g_stats[128];
__device__ float g_scale[64];
__device__ float g_shift[64];
__device__ int   g_is64;

// ---------------- helpers ----------------
__device__ __forceinline__ void red4(float* p, float a, float b, float c, float d) {
    asm volatile("red.global.add.v4.f32 [%0], {%1,%2,%3,%4};"
                 :: "l"(p), "f"(a), "f"(b), "f"(c), "f"(d) : "memory");
}
__device__ __forceinline__ float sigmoidf_(float x) {
    float t;
    asm("tanh.approx.f32 %0, %1;" : "=f"(t) : "f"(0.5f * x));
    return fmaf(0.5f, t, 0.5f);
}
__device__ __forceinline__ float softplusf_(float x) {
    return (x > 15.0f) ? x : __logf(1.0f + __expf(x));
}
__device__ __forceinline__ unsigned int pkh2(float lo, float hi) {
    __half2 h = __floats2half2_rn(lo, hi);
    return *reinterpret_cast<unsigned int*>(&h);
}
__device__ __forceinline__ void mma_f16(float d[4],
                                        unsigned int a0, unsigned int a1,
                                        unsigned int a2, unsigned int a3,
                                        unsigned int b0, unsigned int b1) {
    asm volatile(
        "mma.sync.aligned.m16n8k16.row.col.f32.f16.f16.f32 "
        "{%0,%1,%2,%3}, {%4,%5,%6,%7}, {%8,%9}, {%0,%1,%2,%3};"
        : "+f"(d[0]), "+f"(d[1]), "+f"(d[2]), "+f"(d[3])
        : "r"(a0), "r"(a1), "r"(a2), "r"(a3), "r"(b0), "r"(b1));
}
__device__ __forceinline__ void ldsm4(uint4& r, unsigned int addr) {
    asm volatile("ldmatrix.sync.aligned.m8n8.x4.shared.b16 {%0,%1,%2,%3}, [%4];"
                 : "=r"(r.x), "=r"(r.y), "=r"(r.z), "=r"(r.w) : "r"(addr));
}

// ---------------- kernel 0: dtype detect + one-time permuted fp16 weight tiles ----
__global__ void prep_B(const float* __restrict__ Wf, const float* __restrict__ Ws,
                       const unsigned int* __restrict__ ei32) {
    __shared__ unsigned int acc;
    int tid = threadIdx.x;
    if (tid == 0) acc = 0u;
    __syncthreads();
    unsigned int v = 0u;
    for (int i = tid; i < 1024; i += 256) v |= ei32[2 * i + 1];
    atomicOr(&acc, v);

    // edge tile: 2048 entries (rows 128..159 of Wf/Ws)
#pragma unroll
    for (int it = 0; it < 8; ++it) {
        int i = it * 256 + tid;
        int kp = i >> 7, c = i & 127;
        int sec = c >> 6, cc = c & 63;
        const float* W = sec ? Ws : Wf;
        float v0 = W[(128 + 2 * kp) * 64 + cc];
        float v1 = W[(129 + 2 * kp) * 64 + cc];
        int w = cc >> 5, L32 = cc & 31;
        int g = L32 >> 4, L = L32 & 15;
        int t = L >> 2, u = L & 3;
        int p = sec * 64 + w * 32 + (2 * g + (u >> 1)) * 8 + 2 * t + (u & 1);
        g_Bh[p * 16 + kp] = pkh2(v0, v1);
    }
    // node tile: 8192 entries
#pragma unroll
    for (int it = 0; it < 32; ++it) {
        int i = it * 256 + tid;
        int kp = i & 31, c = i >> 5;
        int sec = c >> 6, cs = c & 63;
        const float* W = (sec & 1) ? Ws : Wf;
        int rbase = (sec >> 1) * 64 + 2 * kp;
        float v0 = W[rbase * 64 + cs];
        float v1 = W[(rbase + 1) * 64 + cs];
        int h128 = c >> 7, cL = c & 127;
        int g = cL >> 4, L = cL & 15, t = L >> 2, u = L & 3;
        int p = h128 * 128 + (2 * g + (u >> 1)) * 8 + 2 * t + (u & 1);
        g_Bn[p * 32 + kp] = pkh2(v0, v1);
    }
    __syncthreads();
    if (tid == 0) g_is64 = (acc == 0u) ? 1 : 0;
}

// ---------------- kernel 1: node projection via fp16 ldmatrix MMA ----------------
// (unchanged from R14 winner)
__global__ void __launch_bounds__(256, 2) node_gemm(
    const float* __restrict__ node, const float* __restrict__ bf,
    const float* __restrict__ bs)
{
    __shared__ alignas(16) unsigned int Asm[64 * 36];
    __shared__ alignas(16) unsigned int Bsm[256 * 36];

    const int tid = threadIdx.x;
    const int nb0 = blockIdx.x * 64;

    {
        int n = tid >> 2, k16 = tid & 3;
        int gn = nb0 + n;
        float4 v0, v1, v2, v3;
        if (gn < N_NODES) {
            const float4* s4 = (const float4*)(node + (size_t)gn * 64 + k16 * 16);
            v0 = s4[0]; v1 = s4[1]; v2 = s4[2]; v3 = s4[3];
        } else {
            v0 = v1 = v2 = v3 = make_float4(0.f, 0.f, 0.f, 0.f);
        }
        uint4 o0 = make_uint4(pkh2(v0.x, v0.y), pkh2(v0.z, v0.w),
                              pkh2(v1.x, v1.y), pkh2(v1.z, v1.w));
        uint4 o1 = make_uint4(pkh2(v2.x, v2.y), pkh2(v2.z, v2.w),
                              pkh2(v3.x, v3.y), pkh2(v3.z, v3.w));
        *(uint4*)&Asm[n * 36 + k16 * 8]     = o0;
        *(uint4*)&Asm[n * 36 + k16 * 8 + 4] = o1;
    }
#pragma unroll
    for (int it = 0; it < 8; ++it) {
        int c = it * 256 + tid;
        int p = c >> 3, k4 = c & 7;
        *(uint4*)&Bsm[p * 36 + k4 * 4] = ((const uint4*)g_Bn)[c];
    }
    __syncthreads();

    const int warp = tid >> 5, lane = tid & 31;
    const int eg = warp & 3;
    const int cg = warp >> 2;
    const int gid = lane >> 2, tig = lane & 3;
    const int quad = lane >> 3, rin = lane & 7;
    const int nbase = eg * 16;

    const unsigned int a_base = (unsigned int)__cvta_generic_to_shared(Asm);
    const unsigned int b_base = (unsigned int)__cvta_generic_to_shared(Bsm);

    const unsigned int a_addr =
        a_base + (nbase + (quad & 1) * 8 + rin) * 144 + (quad >> 1) * 16;
    uint4 afr[4];
#pragma unroll
    for (int ks = 0; ks < 4; ++ks) ldsm4(afr[ks], a_addr + ks * 32);

    unsigned int b_addr[8];
#pragma unroll
    for (int np = 0; np < 8; ++np)
        b_addr[np] = b_base + (cg * 128 + np * 16 + (quad >> 1) * 8 + rin) * 144
                   + (quad & 1) * 16;

    float d[16][4];
#pragma unroll
    for (int nb = 0; nb < 16; ++nb)
#pragma unroll
        for (int j = 0; j < 4; ++j) d[nb][j] = 0.0f;

#pragma unroll
    for (int ks = 0; ks < 4; ++ks) {
        uint4 av = afr[ks];
#pragma unroll
        for (int np = 0; np < 8; ++np) {
            uint4 bv;
            ldsm4(bv, b_addr[np] + ks * 32);
            mma_f16(d[2 * np],     av.x, av.y, av.z, av.w, bv.x, bv.y);
            mma_f16(d[2 * np + 1], av.x, av.y, av.z, av.w, bv.z, bv.w);
        }
    }

#pragma unroll
    for (int r = 0; r < 2; ++r) {
        int gn = nb0 + nbase + gid + r * 8;
        if (gn < N_NODES) {
            __half* dst = g_NPh + (size_t)gn * 256;
#pragma unroll
            for (int g = 0; g < 8; ++g) {
                int cL = cg * 128 + 16 * g + 4 * tig;
                int sec = cL >> 6, cs = cL & 63;
                float b0 = 0.f, b1 = 0.f, b2 = 0.f, b3 = 0.f;
                if (sec == 0) {
                    float4 bb = *(const float4*)(bf + cs);
                    b0 = bb.x; b1 = bb.y; b2 = bb.z; b3 = bb.w;
                } else if (sec == 1) {
                    float4 bb = *(const float4*)(bs + cs);
                    b0 = bb.x; b1 = bb.y; b2 = bb.z; b3 = bb.w;
                }
                float v0 = d[2 * g][2 * r]         + b0;
                float v1 = d[2 * g][2 * r + 1]     + b1;
                float v2 = d[2 * g + 1][2 * r]     + b2;
                float v3 = d[2 * g + 1][2 * r + 1] + b3;
                uint2 o = make_uint2(pkh2(v0, v1), pkh2(v2, v3));
                int idx = (sec >> 1) * 128 + (cs >> 2) * 8 + (sec & 1) * 4;
                *(uint2*)&dst[idx] = o;
            }
        }
    }
}

// ---------------- kernel 2: fp16 ldmatrix tensor-core edge GEMM ----------------
// 128 edges/block, 512 threads (16 warps), launch_bounds(512,2) -> 32 warps/SM.
// Same warp tile / mainloop / epilogue as R14; B fill amortized over 2x edges.
__global__ void __launch_bounds__(512, 2) edge_fused(
    const float* __restrict__ ea, const void* __restrict__ ei,
    int eb_base)
{
    __shared__ alignas(16) unsigned int Asm[128 * 20];
    __shared__ alignas(16) unsigned int Bsm[128 * 20];
    __shared__ int s_src[128], s_tgt[128];

    const int tid = threadIdx.x;
    const int eb = eb_base + blockIdx.x * 128;

    if (tid < 128) {
        int src, tgt;
        if (g_is64) {
            src = (int)((const long long*)ei)[eb + tid];
            tgt = (int)((const long long*)ei)[N_EDGES + eb + tid];
        } else {
            src = ((const int*)ei)[eb + tid];
            tgt = ((const int*)ei)[N_EDGES + eb + tid];
        }
        s_src[tid] = src;
        s_tgt[tid] = tgt;
    }

    // A fill: edge e = tid>>2 (0..127), quad k4 = tid&3
    {
        int e = tid >> 2, k4 = tid & 3;
        const float4* src4 = (const float4*)(ea + (size_t)(eb + e) * 32 + k4 * 8);
        float4 v0 = src4[0], v1 = src4[1];
        uint4 o = make_uint4(pkh2(v0.x, v0.y), pkh2(v0.z, v0.w),
                             pkh2(v1.x, v1.y), pkh2(v1.z, v1.w));
        *(uint4*)&Asm[e * 20 + k4 * 4] = o;
    }
    // B fill: 512 uint4 chunks, one per thread
    {
        int c = tid;
        int p = c >> 2, k4 = c & 3;
        *(uint4*)&Bsm[p * 20 + k4 * 4] = ((const uint4*)g_Bh)[c];
    }
    __syncthreads();

    const int warp = tid >> 5, lane = tid & 31;
    const int eg = warp >> 1;        // edge group (16 of 128 edges)
    const int cg = warp & 1;         // col half
    const int gid = lane >> 2;
    const int tig = lane & 3;
    const int ebase = eg * 16;
    const int quad = lane >> 3, rin = lane & 7;

    const unsigned int a_base = (unsigned int)__cvta_generic_to_shared(Asm);
    const unsigned int b_base = (unsigned int)__cvta_generic_to_shared(Bsm);

    const unsigned int a_addr =
        a_base + (ebase + (quad & 1) * 8 + rin) * 80 + ((quad >> 1) * 8) * 2;
    uint4 afr[2];
    ldsm4(afr[0], a_addr);
    ldsm4(afr[1], a_addr + 32);

    unsigned int b_addr[4];
#pragma unroll
    for (int np = 0; np < 4; ++np) {
        int sec = np >> 1;
        int row = sec * 64 + cg * 32 + ((2 * np) & 3) * 8 + (quad >> 1) * 8 + rin;
        b_addr[np] = b_base + row * 80 + ((quad & 1) * 8) * 2;
    }

    float d[8][4];
#pragma unroll
    for (int nb = 0; nb < 8; ++nb)
#pragma unroll
        for (int j = 0; j < 4; ++j) d[nb][j] = 0.0f;

#pragma unroll
    for (int ks = 0; ks < 2; ++ks) {
        uint4 av = afr[ks];
#pragma unroll
        for (int np = 0; np < 4; ++np) {
            uint4 bv;
            ldsm4(bv, b_addr[np] + ks * 32);
            mma_f16(d[2 * np],     av.x, av.y, av.z, av.w, bv.x, bv.y);
            mma_f16(d[2 * np + 1], av.x, av.y, av.z, av.w, bv.z, bv.w);
        }
    }

#pragma unroll
    for (int r = 0; r < 2; ++r) {
        const int el = ebase + gid + r * 8;
        const int src = s_src[el], tgt = s_tgt[el];
        const uint4* ps = (const uint4*)(g_NPh + (size_t)src * 256);
        const uint4* pt = (const uint4*)(g_NPh + (size_t)tgt * 256 + 128);
#pragma unroll
        for (int g = 0; g < 2; ++g) {
            const int cL = cg * 32 + 16 * g + 4 * tig;
            const int q = cL >> 2;
            uint4 vs = ps[q];
            uint4 vt = pt[q];

            float2 sf0 = __half22float2(*(const __half2*)&vs.x);
            float2 sf1 = __half22float2(*(const __half2*)&vs.y);
            float2 ss0 = __half22float2(*(const __half2*)&vs.z);
            float2 ss1 = __half22float2(*(const __half2*)&vs.w);
            float2 tf0 = __half22float2(*(const __half2*)&vt.x);
            float2 tf1 = __half22float2(*(const __half2*)&vt.y);
            float2 ts0 = __half22float2(*(const __half2*)&vt.z);
            float2 ts1 = __half22float2(*(const __half2*)&vt.w);

            float fv0 = d[2 * g][2 * r]         + sf0.x + tf0.x;
            float fv1 = d[2 * g][2 * r + 1]     + sf0.y + tf0.y;
            float fv2 = d[2 * g + 1][2 * r]     + sf1.x + tf1.x;
            float fv3 = d[2 * g + 1][2 * r + 1] + sf1.y + tf1.y;
            float sv0 = d[4 + 2 * g][2 * r]         + ss0.x + ts0.x;
            float sv1 = d[4 + 2 * g][2 * r + 1]     + ss0.y + ts0.y;
            float sv2 = d[4 + 2 * g + 1][2 * r]     + ss1.x + ts1.x;
            float sv3 = d[4 + 2 * g + 1][2 * r + 1] + ss1.y + ts1.y;

            float h0 = sigmoidf_(fv0) * softplusf_(sv0);
            float h1 = sigmoidf_(fv1) * softplusf_(sv1);
            float h2 = sigmoidf_(fv2) * softplusf_(sv2);
            float h3 = sigmoidf_(fv3) * softplusf_(sv3);

            red4(g_msg + (size_t)src * 64 + cL, h0, h1, h2, h3);
        }
    }
}

// ---------------- kernel 3: BN statistics reduction ----------------
__global__ void __launch_bounds__(256) bn_reduce() {
    __shared__ float shs[16][68];
    __shared__ float sh2[16][68];
    const int tid = threadIdx.x;
    const int cg = tid & 15;
    const int ng = tid >> 4;

    float4 s  = make_float4(0.f, 0.f, 0.f, 0.f);
    float4 s2 = make_float4(0.f, 0.f, 0.f, 0.f);
    for (int n = blockIdx.x * 16 + ng; n < N_NODES; n += gridDim.x * 16) {
        float4 v = *(const float4*)(g_msg + (size_t)n * 64 + cg * 4);
        s.x += v.x; s.y += v.y; s.z += v.z; s.w += v.w;
        s2.x += v.x * v.x; s2.y += v.y * v.y; s2.z += v.z * v.z; s2.w += v.w * v.w;
    }
    *(float4*)&shs[ng][cg * 4] = s;
    *(float4*)&sh2[ng][cg * 4] = s2;
    __syncthreads();
    if (tid < 64) {
        float a = 0.f, b = 0.f;
#pragma unroll
        for (int g = 0; g < 16; ++g) { a += shs[g][tid]; b += sh2[g][tid]; }
        atomicAdd(&g_stats[tid], (double)a);
        atomicAdd(&g_stats[64 + tid], (double)b);
    }
}

__global__ void bn_stats(const float* __restrict__ gamma, const float* __restrict__ beta) {
    int f = threadIdx.x;
    double invN = 1.0 / (double)N_NODES;
    double mean = g_stats[f] * invN;
    double var = g_stats[64 + f] * invN - mean * mean;
    if (var < 0.0) var = 0.0;
    float sc = (float)(rsqrt(var + 1e-5) * (double)gamma[f]);
    g_scale[f] = sc;
    g_shift[f] = beta[f] - (float)mean * sc;
}

// ---------------- kernel 4: residual + affine BN apply ----------------
__global__ void finalize(const float* __restrict__ node, float* __restrict__ out) {
    int idx = blockIdx.x * blockDim.x + threadIdx.x;
    float4 m = ((const float4*)g_msg)[idx];
    float4 x = ((const float4*)node)[idx];
    int f0 = (idx * 4) & 63;
    float4 r;
    r.x = x.x + m.x * g_scale[f0]     + g_shift[f0];
    r.y = x.y + m.y * g_scale[f0 + 1] + g_shift[f0 + 1];
    r.z = x.z + m.z * g_scale[f0 + 2] + g_shift[f0 + 2];
    r.w = x.w + m.w * g_scale[f0 + 3] + g_shift[f0 + 3];
    ((float4*)out)[idx] = r;
}

// ---------------- launch ----------------
extern "C" void kernel_launch(void* const* d_in, const int* in_sizes, int n_in,
                              void* d_out, int out_size) {
    const float* node  = (const float*)d_in[0];
    const void*  ei    = d_in[1];
    const float* ea    = (const float*)d_in[2];
    const float* Wf    = (const float*)d_in[3];
    const float* bf    = (const float*)d_in[4];
    const float* Ws    = (const float*)d_in[5];
    const float* bs    = (const float*)d_in[6];
    const float* gamma = (const float*)d_in[7];
    const float* beta  = (const float*)d_in[8];
    float* out = (float*)d_out;

    void* pmsg = nullptr; void* pstats = nullptr;
    cudaGetSymbolAddress(&pmsg, g_msg);
    cudaGetSymbolAddress(&pstats, g_stats);
    cudaMemsetAsync(pmsg, 0, (size_t)N_NODES * 64 * sizeof(float));   // 1
    cudaMemsetAsync(pstats, 0, 128 * sizeof(double));                 // 2

    const int HALF_BLOCKS = N_EDGES / 128 / 2;   // 6250 blocks per half

    prep_B<<<1, 256>>>(Wf, Ws, (const unsigned int*)ei);              // 3
    node_gemm<<<(N_NODES + 63) / 64, 256>>>(node, bf, bs);            // 4
    edge_fused<<<HALF_BLOCKS, 512>>>(ea, ei, 0);                      // 5
    edge_fused<<<HALF_BLOCKS, 512>>>(ea, ei, HALF_BLOCKS * 128);      // 6  <- ncu slot
    bn_reduce<<<592, 256>>>();
    bn_stats<<<1, 64>>>(gamma, beta);
    finalize<<<(N_NODES * 64) / 1024, 256>>>(node, out);
}

// round 16
// speedup vs baseline: 1.0382x; 1.0382x over previous
#include <cuda_runtime.h>
#include <cuda_fp16.h>
#include <cstdint>
#include <cstddef>

#define N_NODES 100000
#define N_EDGES 1600000

// ---------------- scratch ----------------
// g_NPh interleaved layout per node (256 halfs):
//   [0:128)   src part : for q in 0..15: halves 8q..8q+3 = f cols 4q..4q+3,
//                                         halves 8q+4..8q+7 = s cols 4q..4q+3
//   [128:256) tgt part : same structure
__device__ __align__(16) __half g_NPh[(size_t)N_NODES * 256];
__device__ __align__(16) float g_msg[(size_t)N_NODES * 64];
__device__ __align__(16) unsigned int g_Bh[128 * 16];   // permuted fp16 edge-B tile
__device__ __align__(16) unsigned int g_Bn[256 * 32];   // permuted fp16 node-W tile
__device__ double g_stats[128];
__device__ float g_scale[64];
__device__ float g_shift[64];
__device__ int   g_is64;

// ---------------- helpers ----------------
__device__ __forceinline__ void red4(float* p, float a, float b, float c, float d) {
    asm volatile("red.global.add.v4.f32 [%0], {%1,%2,%3,%4};"
                 :: "l"(p), "f"(a), "f"(b), "f"(c), "f"(d) : "memory");
}
__device__ __forceinline__ float sigmoidf_(float x) {
    float t;
    asm("tanh.approx.f32 %0, %1;" : "=f"(t) : "f"(0.5f * x));
    return fmaf(0.5f, t, 0.5f);
}
__device__ __forceinline__ float softplusf_(float x) {
    return (x > 15.0f) ? x : __logf(1.0f + __expf(x));
}
__device__ __forceinline__ unsigned int pkh2(float lo, float hi) {
    __half2 h = __floats2half2_rn(lo, hi);
    return *reinterpret_cast<unsigned int*>(&h);
}
__device__ __forceinline__ void mma_f16(float d[4],
                                        unsigned int a0, unsigned int a1,
                                        unsigned int a2, unsigned int a3,
                                        unsigned int b0, unsigned int b1) {
    asm volatile(
        "mma.sync.aligned.m16n8k16.row.col.f32.f16.f16.f32 "
        "{%0,%1,%2,%3}, {%4,%5,%6,%7}, {%8,%9}, {%0,%1,%2,%3};"
        : "+f"(d[0]), "+f"(d[1]), "+f"(d[2]), "+f"(d[3])
        : "r"(a0), "r"(a1), "r"(a2), "r"(a3), "r"(b0), "r"(b1));
}
__device__ __forceinline__ void ldsm4(uint4& r, unsigned int addr) {
    asm volatile("ldmatrix.sync.aligned.m8n8.x4.shared.b16 {%0,%1,%2,%3}, [%4];"
                 : "=r"(r.x), "=r"(r.y), "=r"(r.z), "=r"(r.w) : "r"(addr));
}

// ---------------- kernel 0: dtype detect + one-time permuted fp16 weight tiles ----
__global__ void prep_B(const float* __restrict__ Wf, const float* __restrict__ Ws,
                       const unsigned int* __restrict__ ei32) {
    __shared__ unsigned int acc;
    int tid = threadIdx.x;
    if (tid == 0) acc = 0u;
    __syncthreads();
    unsigned int v = 0u;
    for (int i = tid; i < 1024; i += 256) v |= ei32[2 * i + 1];
    atomicOr(&acc, v);

    // edge tile: 2048 entries (rows 128..159 of Wf/Ws)
#pragma unroll
    for (int it = 0; it < 8; ++it) {
        int i = it * 256 + tid;
        int kp = i >> 7, c = i & 127;
        int sec = c >> 6, cc = c & 63;
        const float* W = sec ? Ws : Wf;
        float v0 = W[(128 + 2 * kp) * 64 + cc];
        float v1 = W[(129 + 2 * kp) * 64 + cc];
        int w = cc >> 5, L32 = cc & 31;
        int g = L32 >> 4, L = L32 & 15;
        int t = L >> 2, u = L & 3;
        int p = sec * 64 + w * 32 + (2 * g + (u >> 1)) * 8 + 2 * t + (u & 1);
        g_Bh[p * 16 + kp] = pkh2(v0, v1);
    }
    // node tile: 8192 entries
#pragma unroll
    for (int it = 0; it < 32; ++it) {
        int i = it * 256 + tid;
        int kp = i & 31, c = i >> 5;
        int sec = c >> 6, cs = c & 63;
        const float* W = (sec & 1) ? Ws : Wf;
        int rbase = (sec >> 1) * 64 + 2 * kp;
        float v0 = W[rbase * 64 + cs];
        float v1 = W[(rbase + 1) * 64 + cs];
        int h128 = c >> 7, cL = c & 127;
        int g = cL >> 4, L = cL & 15, t = L >> 2, u = L & 3;
        int p = h128 * 128 + (2 * g + (u >> 1)) * 8 + 2 * t + (u & 1);
        g_Bn[p * 32 + kp] = pkh2(v0, v1);
    }
    __syncthreads();
    if (tid == 0) g_is64 = (acc == 0u) ? 1 : 0;
}

// ---------------- kernel 1: node projection via fp16 ldmatrix MMA ----------------
__global__ void __launch_bounds__(256, 2) node_gemm(
    const float* __restrict__ node, const float* __restrict__ bf,
    const float* __restrict__ bs)
{
    __shared__ alignas(16) unsigned int Asm[64 * 36];
    __shared__ alignas(16) unsigned int Bsm[256 * 36];

    const int tid = threadIdx.x;
    const int nb0 = blockIdx.x * 64;

    {
        int n = tid >> 2, k16 = tid & 3;
        int gn = nb0 + n;
        float4 v0, v1, v2, v3;
        if (gn < N_NODES) {
            const float4* s4 = (const float4*)(node + (size_t)gn * 64 + k16 * 16);
            v0 = s4[0]; v1 = s4[1]; v2 = s4[2]; v3 = s4[3];
        } else {
            v0 = v1 = v2 = v3 = make_float4(0.f, 0.f, 0.f, 0.f);
        }
        uint4 o0 = make_uint4(pkh2(v0.x, v0.y), pkh2(v0.z, v0.w),
                              pkh2(v1.x, v1.y), pkh2(v1.z, v1.w));
        uint4 o1 = make_uint4(pkh2(v2.x, v2.y), pkh2(v2.z, v2.w),
                              pkh2(v3.x, v3.y), pkh2(v3.z, v3.w));
        *(uint4*)&Asm[n * 36 + k16 * 8]     = o0;
        *(uint4*)&Asm[n * 36 + k16 * 8 + 4] = o1;
    }
#pragma unroll
    for (int it = 0; it < 8; ++it) {
        int c = it * 256 + tid;
        int p = c >> 3, k4 = c & 7;
        *(uint4*)&Bsm[p * 36 + k4 * 4] = ((const uint4*)g_Bn)[c];
    }
    __syncthreads();

    const int warp = tid >> 5, lane = tid & 31;
    const int eg = warp & 3;
    const int cg = warp >> 2;
    const int gid = lane >> 2, tig = lane & 3;
    const int quad = lane >> 3, rin = lane & 7;
    const int nbase = eg * 16;

    const unsigned int a_base = (unsigned int)__cvta_generic_to_shared(Asm);
    const unsigned int b_base = (unsigned int)__cvta_generic_to_shared(Bsm);

    const unsigned int a_addr =
        a_base + (nbase + (quad & 1) * 8 + rin) * 144 + (quad >> 1) * 16;
    uint4 afr[4];
#pragma unroll
    for (int ks = 0; ks < 4; ++ks) ldsm4(afr[ks], a_addr + ks * 32);

    unsigned int b_addr[8];
#pragma unroll
    for (int np = 0; np < 8; ++np)
        b_addr[np] = b_base + (cg * 128 + np * 16 + (quad >> 1) * 8 + rin) * 144
                   + (quad & 1) * 16;

    float d[16][4];
#pragma unroll
    for (int nb = 0; nb < 16; ++nb)
#pragma unroll
        for (int j = 0; j < 4; ++j) d[nb][j] = 0.0f;

#pragma unroll
    for (int ks = 0; ks < 4; ++ks) {
        uint4 av = afr[ks];
#pragma unroll
        for (int np = 0; np < 8; ++np) {
            uint4 bv;
            ldsm4(bv, b_addr[np] + ks * 32);
            mma_f16(d[2 * np],     av.x, av.y, av.z, av.w, bv.x, bv.y);
            mma_f16(d[2 * np + 1], av.x, av.y, av.z, av.w, bv.z, bv.w);
        }
    }

#pragma unroll
    for (int r = 0; r < 2; ++r) {
        int gn = nb0 + nbase + gid + r * 8;
        if (gn < N_NODES) {
            __half* dst = g_NPh + (size_t)gn * 256;
#pragma unroll
            for (int g = 0; g < 8; ++g) {
                int cL = cg * 128 + 16 * g + 4 * tig;
                int sec = cL >> 6, cs = cL & 63;
                float b0 = 0.f, b1 = 0.f, b2 = 0.f, b3 = 0.f;
                if (sec == 0) {
                    float4 bb = *(const float4*)(bf + cs);
                    b0 = bb.x; b1 = bb.y; b2 = bb.z; b3 = bb.w;
                } else if (sec == 1) {
                    float4 bb = *(const float4*)(bs + cs);
                    b0 = bb.x; b1 = bb.y; b2 = bb.z; b3 = bb.w;
                }
                float v0 = d[2 * g][2 * r]         + b0;
                float v1 = d[2 * g][2 * r + 1]     + b1;
                float v2 = d[2 * g + 1][2 * r]     + b2;
                float v3 = d[2 * g + 1][2 * r + 1] + b3;
                uint2 o = make_uint2(pkh2(v0, v1), pkh2(v2, v3));
                int idx = (sec >> 1) * 128 + (cs >> 2) * 8 + (sec & 1) * 4;
                *(uint2*)&dst[idx] = o;
            }
        }
    }
}

// ---------------- kernel 2: fp16 ldmatrix tensor-core edge GEMM ----------------
// R14 config (best known): 64 edges/block, 256 threads, launch_bounds(256,4).
// tanh-based sigmoid retained (validated R15: accuracy unchanged, fewer MUFU).
__global__ void __launch_bounds__(256, 4) edge_fused(
    const float* __restrict__ ea, const void* __restrict__ ei,
    int eb_base)
{
    __shared__ alignas(16) unsigned int Asm[64 * 20];
    __shared__ alignas(16) unsigned int Bsm[128 * 20];
    __shared__ int s_src[64], s_tgt[64];

    const int tid = threadIdx.x;
    const int eb = eb_base + blockIdx.x * 64;

    if (tid < 64) {
        int src, tgt;
        if (g_is64) {
            src = (int)((const long long*)ei)[eb + tid];
            tgt = (int)((const long long*)ei)[N_EDGES + eb + tid];
        } else {
            src = ((const int*)ei)[eb + tid];
            tgt = ((const int*)ei)[N_EDGES + eb + tid];
        }
        s_src[tid] = src;
        s_tgt[tid] = tgt;
    }

    {
        int e = tid >> 2, k4 = tid & 3;
        const float4* src4 = (const float4*)(ea + (size_t)(eb + e) * 32 + k4 * 8);
        float4 v0 = src4[0], v1 = src4[1];
        uint4 o = make_uint4(pkh2(v0.x, v0.y), pkh2(v0.z, v0.w),
                             pkh2(v1.x, v1.y), pkh2(v1.z, v1.w));
        *(uint4*)&Asm[e * 20 + k4 * 4] = o;
    }
#pragma unroll
    for (int it = 0; it < 2; ++it) {
        int c = it * 256 + tid;
        int p = c >> 2, k4 = c & 3;
        *(uint4*)&Bsm[p * 20 + k4 * 4] = ((const uint4*)g_Bh)[c];
    }
    __syncthreads();

    const int warp = tid >> 5, lane = tid & 31;
    const int eg = warp >> 1;
    const int cg = warp & 1;
    const int gid = lane >> 2;
    const int tig = lane & 3;
    const int ebase = eg * 16;
    const int quad = lane >> 3, rin = lane & 7;

    const unsigned int a_base = (unsigned int)__cvta_generic_to_shared(Asm);
    const unsigned int b_base = (unsigned int)__cvta_generic_to_shared(Bsm);

    const unsigned int a_addr =
        a_base + (ebase + (quad & 1) * 8 + rin) * 80 + ((quad >> 1) * 8) * 2;
    uint4 afr[2];
    ldsm4(afr[0], a_addr);
    ldsm4(afr[1], a_addr + 32);

    unsigned int b_addr[4];
#pragma unroll
    for (int np = 0; np < 4; ++np) {
        int sec = np >> 1;
        int row = sec * 64 + cg * 32 + ((2 * np) & 3) * 8 + (quad >> 1) * 8 + rin;
        b_addr[np] = b_base + row * 80 + ((quad & 1) * 8) * 2;
    }

    float d[8][4];
#pragma unroll
    for (int nb = 0; nb < 8; ++nb)
#pragma unroll
        for (int j = 0; j < 4; ++j) d[nb][j] = 0.0f;

#pragma unroll
    for (int ks = 0; ks < 2; ++ks) {
        uint4 av = afr[ks];
#pragma unroll
        for (int np = 0; np < 4; ++np) {
            uint4 bv;
            ldsm4(bv, b_addr[np] + ks * 32);
            mma_f16(d[2 * np],     av.x, av.y, av.z, av.w, bv.x, bv.y);
            mma_f16(d[2 * np + 1], av.x, av.y, av.z, av.w, bv.z, bv.w);
        }
    }

#pragma unroll
    for (int r = 0; r < 2; ++r) {
        const int el = ebase + gid + r * 8;
        const int src = s_src[el], tgt = s_tgt[el];
        const uint4* ps = (const uint4*)(g_NPh + (size_t)src * 256);
        const uint4* pt = (const uint4*)(g_NPh + (size_t)tgt * 256 + 128);
#pragma unroll
        for (int g = 0; g < 2; ++g) {
            const int cL = cg * 32 + 16 * g + 4 * tig;
            const int q = cL >> 2;
            uint4 vs = ps[q];
            uint4 vt = pt[q];

            float2 sf0 = __half22float2(*(const __half2*)&vs.x);
            float2 sf1 = __half22float2(*(const __half2*)&vs.y);
            float2 ss0 = __half22float2(*(const __half2*)&vs.z);
            float2 ss1 = __half22float2(*(const __half2*)&vs.w);
            float2 tf0 = __half22float2(*(const __half2*)&vt.x);
            float2 tf1 = __half22float2(*(const __half2*)&vt.y);
            float2 ts0 = __half22float2(*(const __half2*)&vt.z);
            float2 ts1 = __half22float2(*(const __half2*)&vt.w);

            float fv0 = d[2 * g][2 * r]         + sf0.x + tf0.x;
            float fv1 = d[2 * g][2 * r + 1]     + sf0.y + tf0.y;
            float fv2 = d[2 * g + 1][2 * r]     + sf1.x + tf1.x;
            float fv3 = d[2 * g + 1][2 * r + 1] + sf1.y + tf1.y;
            float sv0 = d[4 + 2 * g][2 * r]         + ss0.x + ts0.x;
            float sv1 = d[4 + 2 * g][2 * r + 1]     + ss0.y + ts0.y;
            float sv2 = d[4 + 2 * g + 1][2 * r]     + ss1.x + ts1.x;
            float sv3 = d[4 + 2 * g + 1][2 * r + 1] + ss1.y + ts1.y;

            float h0 = sigmoidf_(fv0) * softplusf_(sv0);
            float h1 = sigmoidf_(fv1) * softplusf_(sv1);
            float h2 = sigmoidf_(fv2) * softplusf_(sv2);
            float h3 = sigmoidf_(fv3) * softplusf_(sv3);

            red4(g_msg + (size_t)src * 64 + cL, h0, h1, h2, h3);
        }
    }
}

// ---------------- kernel 3: BN statistics reduction ----------------
__global__ void __launch_bounds__(256) bn_reduce() {
    __shared__ float shs[16][68];
    __shared__ float sh2[16][68];
    const int tid = threadIdx.x;
    const int cg = tid & 15;
    const int ng = tid >> 4;

    float4 s  = make_float4(0.f, 0.f, 0.f, 0.f);
    float4 s2 = make_float4(0.f, 0.f, 0.f, 0.f);
    for (int n = blockIdx.x * 16 + ng; n < N_NODES; n += gridDim.x * 16) {
        float4 v = *(const float4*)(g_msg + (size_t)n * 64 + cg * 4);
        s.x += v.x; s.y += v.y; s.z += v.z; s.w += v.w;
        s2.x += v.x * v.x; s2.y += v.y * v.y; s2.z += v.z * v.z; s2.w += v.w * v.w;
    }
    *(float4*)&shs[ng][cg * 4] = s;
    *(float4*)&sh2[ng][cg * 4] = s2;
    __syncthreads();
    if (tid < 64) {
        float a = 0.f, b = 0.f;
#pragma unroll
        for (int g = 0; g < 16; ++g) { a += shs[g][tid]; b += sh2[g][tid]; }
        atomicAdd(&g_stats[tid], (double)a);
        atomicAdd(&g_stats[64 + tid], (double)b);
    }
}

__global__ void bn_stats(const float* __restrict__ gamma, const float* __restrict__ beta) {
    int f = threadIdx.x;
    double invN = 1.0 / (double)N_NODES;
    double mean = g_stats[f] * invN;
    double var = g_stats[64 + f] * invN - mean * mean;
    if (var < 0.0) var = 0.0;
    float sc = (float)(rsqrt(var + 1e-5) * (double)gamma[f]);
    g_scale[f] = sc;
    g_shift[f] = beta[f] - (float)mean * sc;
}

// ---------------- kernel 4: residual + affine BN apply ----------------
__global__ void finalize(const float* __restrict__ node, float* __restrict__ out) {
    int idx = blockIdx.x * blockDim.x + threadIdx.x;
    float4 m = ((const float4*)g_msg)[idx];
    float4 x = ((const float4*)node)[idx];
    int f0 = (idx * 4) & 63;
    float4 r;
    r.x = x.x + m.x * g_scale[f0]     + g_shift[f0];
    r.y = x.y + m.y * g_scale[f0 + 1] + g_shift[f0 + 1];
    r.z = x.z + m.z * g_scale[f0 + 2] + g_shift[f0 + 2];
    r.w = x.w + m.w * g_scale[f0 + 3] + g_shift[f0 + 3];
    ((float4*)out)[idx] = r;
}

// ---------------- launch ----------------
extern "C" void kernel_launch(void* const* d_in, const int* in_sizes, int n_in,
                              void* d_out, int out_size) {
    const float* node  = (const float*)d_in[0];
    const void*  ei    = d_in[1];
    const float* ea    = (const float*)d_in[2];
    const float* Wf    = (const float*)d_in[3];
    const float* bf    = (const float*)d_in[4];
    const float* Ws    = (const float*)d_in[5];
    const float* bs    = (const float*)d_in[6];
    const float* gamma = (const float*)d_in[7];
    const float* beta  = (const float*)d_in[8];
    float* out = (float*)d_out;

    void* pmsg = nullptr; void* pstats = nullptr;
    cudaGetSymbolAddress(&pmsg, g_msg);
    cudaGetSymbolAddress(&pstats, g_stats);
    cudaMemsetAsync(pmsg, 0, (size_t)N_NODES * 64 * sizeof(float));   // 1
    cudaMemsetAsync(pstats, 0, 128 * sizeof(double));                 // 2

    const int HALF_BLOCKS = N_EDGES / 64 / 2;   // 12500 blocks per half

    prep_B<<<1, 256>>>(Wf, Ws, (const unsigned int*)ei);              // 3
    node_gemm<<<(N_NODES + 63) / 64, 256>>>(node, bf, bs);            // 4
    edge_fused<<<HALF_BLOCKS, 256>>>(ea, ei, 0);                      // 5
    edge_fused<<<HALF_BLOCKS, 256>>>(ea, ei, HALF_BLOCKS * 64);       // 6  <- ncu slot
    bn_reduce<<<592, 256>>>();
    bn_stats<<<1, 64>>>(gamma, beta);
    finalize<<<(N_NODES * 64) / 1024, 256>>>(node, out);
}

// round 17
// speedup vs baseline: 1.0685x; 1.0292x over previous
#include <cuda_runtime.h>
#include <cuda_fp16.h>
#include <cstdint>
#include <cstddef>

#define N_NODES 100000
#define N_EDGES 1600000

// ---------------- scratch ----------------
// g_NPh interleaved layout per node (256 halfs):
//   [0:128)   src part : for q in 0..15: halves 8q..8q+3 = f cols 4q..4q+3,
//                                         halves 8q+4..8q+7 = s cols 4q..4q+3
//   [128:256) tgt part : same structure
__device__ __align__(16) __half g_NPh[(size_t)N_NODES * 256];
__device__ __align__(16) float g_msg[(size_t)N_NODES * 64];
__device__ __align__(16) unsigned int g_Bh[128 * 16];   // permuted fp16 edge-B tile
__device__ __align__(16) unsigned int g_Bn[256 * 32];   // permuted fp16 node-W tile
__device__ double g_stats[128];
__device__ int   g_is64;

// ---------------- helpers ----------------
__device__ __forceinline__ void red4(float* p, float a, float b, float c, float d) {
    asm volatile("red.global.add.v4.f32 [%0], {%1,%2,%3,%4};"
                 :: "l"(p), "f"(a), "f"(b), "f"(c), "f"(d) : "memory");
}
__device__ __forceinline__ float sigmoidf_(float x) {
    float t;
    asm("tanh.approx.f32 %0, %1;" : "=f"(t) : "f"(0.5f * x));
    return fmaf(0.5f, t, 0.5f);
}
__device__ __forceinline__ float softplusf_(float x) {
    return (x > 15.0f) ? x : __logf(1.0f + __expf(x));
}
__device__ __forceinline__ unsigned int pkh2(float lo, float hi) {
    __half2 h = __floats2half2_rn(lo, hi);
    return *reinterpret_cast<unsigned int*>(&h);
}
__device__ __forceinline__ void mma_f16(float d[4],
                                        unsigned int a0, unsigned int a1,
                                        unsigned int a2, unsigned int a3,
                                        unsigned int b0, unsigned int b1) {
    asm volatile(
        "mma.sync.aligned.m16n8k16.row.col.f32.f16.f16.f32 "
        "{%0,%1,%2,%3}, {%4,%5,%6,%7}, {%8,%9}, {%0,%1,%2,%3};"
        : "+f"(d[0]), "+f"(d[1]), "+f"(d[2]), "+f"(d[3])
        : "r"(a0), "r"(a1), "r"(a2), "r"(a3), "r"(b0), "r"(b1));
}
__device__ __forceinline__ void ldsm4(uint4& r, unsigned int addr) {
    asm volatile("ldmatrix.sync.aligned.m8n8.x4.shared.b16 {%0,%1,%2,%3}, [%4];"
                 : "=r"(r.x), "=r"(r.y), "=r"(r.z), "=r"(r.w) : "r"(addr));
}

// ---------------- kernel 0: dtype detect + weight tiles + g_stats zero ----------
__global__ void prep_B(const float* __restrict__ Wf, const float* __restrict__ Ws,
                       const unsigned int* __restrict__ ei32) {
    __shared__ unsigned int acc;
    int tid = threadIdx.x;
    if (tid == 0) acc = 0u;
    __syncthreads();
    unsigned int v = 0u;
    for (int i = tid; i < 1024; i += 256) v |= ei32[2 * i + 1];
    atomicOr(&acc, v);

    if (tid < 128) g_stats[tid] = 0.0;

    // edge tile: 2048 entries (rows 128..159 of Wf/Ws)
#pragma unroll
    for (int it = 0; it < 8; ++it) {
        int i = it * 256 + tid;
        int kp = i >> 7, c = i & 127;
        int sec = c >> 6, cc = c & 63;
        const float* W = sec ? Ws : Wf;
        float v0 = W[(128 + 2 * kp) * 64 + cc];
        float v1 = W[(129 + 2 * kp) * 64 + cc];
        int w = cc >> 5, L32 = cc & 31;
        int g = L32 >> 4, L = L32 & 15;
        int t = L >> 2, u = L & 3;
        int p = sec * 64 + w * 32 + (2 * g + (u >> 1)) * 8 + 2 * t + (u & 1);
        g_Bh[p * 16 + kp] = pkh2(v0, v1);
    }
    // node tile: 8192 entries
#pragma unroll
    for (int it = 0; it < 32; ++it) {
        int i = it * 256 + tid;
        int kp = i & 31, c = i >> 5;
        int sec = c >> 6, cs = c & 63;
        const float* W = (sec & 1) ? Ws : Wf;
        int rbase = (sec >> 1) * 64 + 2 * kp;
        float v0 = W[rbase * 64 + cs];
        float v1 = W[(rbase + 1) * 64 + cs];
        int h128 = c >> 7, cL = c & 127;
        int g = cL >> 4, L = cL & 15, t = L >> 2, u = L & 3;
        int p = h128 * 128 + (2 * g + (u >> 1)) * 8 + 2 * t + (u & 1);
        g_Bn[p * 32 + kp] = pkh2(v0, v1);
    }
    __syncthreads();
    if (tid == 0) g_is64 = (acc == 0u) ? 1 : 0;
}

// ---------------- kernel 1: node projection via fp16 ldmatrix MMA ----------------
// Also zeroes this block's g_msg rows (replaces the standalone memset;
// stream order guarantees completion before edge_fused atomics).
__global__ void __launch_bounds__(256, 2) node_gemm(
    const float* __restrict__ node, const float* __restrict__ bf,
    const float* __restrict__ bs)
{
    __shared__ alignas(16) unsigned int Asm[64 * 36];
    __shared__ alignas(16) unsigned int Bsm[256 * 36];

    const int tid = threadIdx.x;
    const int nb0 = blockIdx.x * 64;

    // zero g_msg for this block's 64 nodes (1024 float4)
    {
        float4 z = make_float4(0.f, 0.f, 0.f, 0.f);
#pragma unroll
        for (int it = 0; it < 4; ++it) {
            int i = it * 256 + tid;
            int n = nb0 + (i >> 4);
            if (n < N_NODES) ((float4*)g_msg)[(size_t)nb0 * 16 + i] = z;
        }
    }

    {
        int n = tid >> 2, k16 = tid & 3;
        int gn = nb0 + n;
        float4 v0, v1, v2, v3;
        if (gn < N_NODES) {
            const float4* s4 = (const float4*)(node + (size_t)gn * 64 + k16 * 16);
            v0 = s4[0]; v1 = s4[1]; v2 = s4[2]; v3 = s4[3];
        } else {
            v0 = v1 = v2 = v3 = make_float4(0.f, 0.f, 0.f, 0.f);
        }
        uint4 o0 = make_uint4(pkh2(v0.x, v0.y), pkh2(v0.z, v0.w),
                              pkh2(v1.x, v1.y), pkh2(v1.z, v1.w));
        uint4 o1 = make_uint4(pkh2(v2.x, v2.y), pkh2(v2.z, v2.w),
                              pkh2(v3.x, v3.y), pkh2(v3.z, v3.w));
        *(uint4*)&Asm[n * 36 + k16 * 8]     = o0;
        *(uint4*)&Asm[n * 36 + k16 * 8 + 4] = o1;
    }
#pragma unroll
    for (int it = 0; it < 8; ++it) {
        int c = it * 256 + tid;
        int p = c >> 3, k4 = c & 7;
        *(uint4*)&Bsm[p * 36 + k4 * 4] = ((const uint4*)g_Bn)[c];
    }
    __syncthreads();

    const int warp = tid >> 5, lane = tid & 31;
    const int eg = warp & 3;
    const int cg = warp >> 2;
    const int gid = lane >> 2, tig = lane & 3;
    const int quad = lane >> 3, rin = lane & 7;
    const int nbase = eg * 16;

    const unsigned int a_base = (unsigned int)__cvta_generic_to_shared(Asm);
    const unsigned int b_base = (unsigned int)__cvta_generic_to_shared(Bsm);

    const unsigned int a_addr =
        a_base + (nbase + (quad & 1) * 8 + rin) * 144 + (quad >> 1) * 16;
    uint4 afr[4];
#pragma unroll
    for (int ks = 0; ks < 4; ++ks) ldsm4(afr[ks], a_addr + ks * 32);

    unsigned int b_addr[8];
#pragma unroll
    for (int np = 0; np < 8; ++np)
        b_addr[np] = b_base + (cg * 128 + np * 16 + (quad >> 1) * 8 + rin) * 144
                   + (quad & 1) * 16;

    float d[16][4];
#pragma unroll
    for (int nb = 0; nb < 16; ++nb)
#pragma unroll
        for (int j = 0; j < 4; ++j) d[nb][j] = 0.0f;

#pragma unroll
    for (int ks = 0; ks < 4; ++ks) {
        uint4 av = afr[ks];
#pragma unroll
        for (int np = 0; np < 8; ++np) {
            uint4 bv;
            ldsm4(bv, b_addr[np] + ks * 32);
            mma_f16(d[2 * np],     av.x, av.y, av.z, av.w, bv.x, bv.y);
            mma_f16(d[2 * np + 1], av.x, av.y, av.z, av.w, bv.z, bv.w);
        }
    }

#pragma unroll
    for (int r = 0; r < 2; ++r) {
        int gn = nb0 + nbase + gid + r * 8;
        if (gn < N_NODES) {
            __half* dst = g_NPh + (size_t)gn * 256;
#pragma unroll
            for (int g = 0; g < 8; ++g) {
                int cL = cg * 128 + 16 * g + 4 * tig;
                int sec = cL >> 6, cs = cL & 63;
                float b0 = 0.f, b1 = 0.f, b2 = 0.f, b3 = 0.f;
                if (sec == 0) {
                    float4 bb = *(const float4*)(bf + cs);
                    b0 = bb.x; b1 = bb.y; b2 = bb.z; b3 = bb.w;
                } else if (sec == 1) {
                    float4 bb = *(const float4*)(bs + cs);
                    b0 = bb.x; b1 = bb.y; b2 = bb.z; b3 = bb.w;
                }
                float v0 = d[2 * g][2 * r]         + b0;
                float v1 = d[2 * g][2 * r + 1]     + b1;
                float v2 = d[2 * g + 1][2 * r]     + b2;
                float v3 = d[2 * g + 1][2 * r + 1] + b3;
                uint2 o = make_uint2(pkh2(v0, v1), pkh2(v2, v3));
                int idx = (sec >> 1) * 128 + (cs >> 2) * 8 + (sec & 1) * 4;
                *(uint2*)&dst[idx] = o;
            }
        }
    }
}

// ---------------- kernel 2: fp16 ldmatrix tensor-core edge GEMM ----------------
// 128 edges/block processed as TWO 64-edge tiles by 256 threads (launch_bounds
// (256,4) — the validated R14/R16 warp shape). B tile + indices loaded once per
// block; Asm reused across tiles.
__global__ void __launch_bounds__(256, 4) edge_fused(
    const float* __restrict__ ea, const void* __restrict__ ei)
{
    __shared__ alignas(16) unsigned int Asm[64 * 20];
    __shared__ alignas(16) unsigned int Bsm[128 * 20];
    __shared__ int s_src[128], s_tgt[128];

    const int tid = threadIdx.x;
    const int eb = blockIdx.x * 128;

    if (tid < 128) {
        int src, tgt;
        if (g_is64) {
            src = (int)((const long long*)ei)[eb + tid];
            tgt = (int)((const long long*)ei)[N_EDGES + eb + tid];
        } else {
            src = ((const int*)ei)[eb + tid];
            tgt = ((const int*)ei)[N_EDGES + eb + tid];
        }
        s_src[tid] = src;
        s_tgt[tid] = tgt;
    }

    const int efill = tid >> 2, k4 = tid & 3;
    // A fill: tile 0
    {
        const float4* src4 = (const float4*)(ea + (size_t)(eb + efill) * 32 + k4 * 8);
        float4 v0 = src4[0], v1 = src4[1];
        uint4 o = make_uint4(pkh2(v0.x, v0.y), pkh2(v0.z, v0.w),
                             pkh2(v1.x, v1.y), pkh2(v1.z, v1.w));
        *(uint4*)&Asm[efill * 20 + k4 * 4] = o;
    }
    // B fill (once per block)
#pragma unroll
    for (int it = 0; it < 2; ++it) {
        int c = it * 256 + tid;
        int p = c >> 2, kk = c & 3;
        *(uint4*)&Bsm[p * 20 + kk * 4] = ((const uint4*)g_Bh)[c];
    }
    __syncthreads();

    const int warp = tid >> 5, lane = tid & 31;
    const int eg = warp >> 1;
    const int cg = warp & 1;
    const int gid = lane >> 2;
    const int tig = lane & 3;
    const int ebase = eg * 16;
    const int quad = lane >> 3, rin = lane & 7;

    const unsigned int a_base = (unsigned int)__cvta_generic_to_shared(Asm);
    const unsigned int b_base = (unsigned int)__cvta_generic_to_shared(Bsm);

    const unsigned int a_addr =
        a_base + (ebase + (quad & 1) * 8 + rin) * 80 + ((quad >> 1) * 8) * 2;

    unsigned int b_addr[4];
#pragma unroll
    for (int np = 0; np < 4; ++np) {
        int sec = np >> 1;
        int row = sec * 64 + cg * 32 + ((2 * np) & 3) * 8 + (quad >> 1) * 8 + rin;
        b_addr[np] = b_base + row * 80 + ((quad & 1) * 8) * 2;
    }

    for (int t = 0; t < 2; ++t) {
        uint4 afr[2];
        ldsm4(afr[0], a_addr);
        ldsm4(afr[1], a_addr + 32);

        float d[8][4];
#pragma unroll
        for (int nb = 0; nb < 8; ++nb)
#pragma unroll
            for (int j = 0; j < 4; ++j) d[nb][j] = 0.0f;

#pragma unroll
        for (int ks = 0; ks < 2; ++ks) {
            uint4 av = afr[ks];
#pragma unroll
            for (int np = 0; np < 4; ++np) {
                uint4 bv;
                ldsm4(bv, b_addr[np] + ks * 32);
                mma_f16(d[2 * np],     av.x, av.y, av.z, av.w, bv.x, bv.y);
                mma_f16(d[2 * np + 1], av.x, av.y, av.z, av.w, bv.z, bv.w);
            }
        }
        __syncthreads();   // all warps done reading Asm (tile t)

        if (t == 0) {
            // refill Asm with tile 1 (epilogue below doesn't touch Asm)
            const float4* src4 =
                (const float4*)(ea + (size_t)(eb + 64 + efill) * 32 + k4 * 8);
            float4 v0 = src4[0], v1 = src4[1];
            uint4 o = make_uint4(pkh2(v0.x, v0.y), pkh2(v0.z, v0.w),
                                 pkh2(v1.x, v1.y), pkh2(v1.z, v1.w));
            *(uint4*)&Asm[efill * 20 + k4 * 4] = o;
        }

        // epilogue for tile t
#pragma unroll
        for (int r = 0; r < 2; ++r) {
            const int el = t * 64 + ebase + gid + r * 8;
            const int src = s_src[el], tgt = s_tgt[el];
            const uint4* ps = (const uint4*)(g_NPh + (size_t)src * 256);
            const uint4* pt = (const uint4*)(g_NPh + (size_t)tgt * 256 + 128);
#pragma unroll
            for (int g = 0; g < 2; ++g) {
                const int cL = cg * 32 + 16 * g + 4 * tig;
                const int q = cL >> 2;
                uint4 vs = ps[q];
                uint4 vt = pt[q];

                float2 sf0 = __half22float2(*(const __half2*)&vs.x);
                float2 sf1 = __half22float2(*(const __half2*)&vs.y);
                float2 ss0 = __half22float2(*(const __half2*)&vs.z);
                float2 ss1 = __half22float2(*(const __half2*)&vs.w);
                float2 tf0 = __half22float2(*(const __half2*)&vt.x);
                float2 tf1 = __half22float2(*(const __half2*)&vt.y);
                float2 ts0 = __half22float2(*(const __half2*)&vt.z);
                float2 ts1 = __half22float2(*(const __half2*)&vt.w);

                float fv0 = d[2 * g][2 * r]         + sf0.x + tf0.x;
                float fv1 = d[2 * g][2 * r + 1]     + sf0.y + tf0.y;
                float fv2 = d[2 * g + 1][2 * r]     + sf1.x + tf1.x;
                float fv3 = d[2 * g + 1][2 * r + 1] + sf1.y + tf1.y;
                float sv0 = d[4 + 2 * g][2 * r]         + ss0.x + ts0.x;
                float sv1 = d[4 + 2 * g][2 * r + 1]     + ss0.y + ts0.y;
                float sv2 = d[4 + 2 * g + 1][2 * r]     + ss1.x + ts1.x;
                float sv3 = d[4 + 2 * g + 1][2 * r + 1] + ss1.y + ts1.y;

                float h0 = sigmoidf_(fv0) * softplusf_(sv0);
                float h1 = sigmoidf_(fv1) * softplusf_(sv1);
                float h2 = sigmoidf_(fv2) * softplusf_(sv2);
                float h3 = sigmoidf_(fv3) * softplusf_(sv3);

                red4(g_msg + (size_t)src * 64 + cL, h0, h1, h2, h3);
            }
        }
        if (t == 0) __syncthreads();   // tile-1 Asm visible to all warps
    }
}

// ---------------- kernel 3: BN statistics reduction ----------------
__global__ void __launch_bounds__(256) bn_reduce() {
    __shared__ float shs[16][68];
    __shared__ float sh2[16][68];
    const int tid = threadIdx.x;
    const int cg = tid & 15;
    const int ng = tid >> 4;

    float4 s  = make_float4(0.f, 0.f, 0.f, 0.f);
    float4 s2 = make_float4(0.f, 0.f, 0.f, 0.f);
    for (int n = blockIdx.x * 16 + ng; n < N_NODES; n += gridDim.x * 16) {
        float4 v = *(const float4*)(g_msg + (size_t)n * 64 + cg * 4);
        s.x += v.x; s.y += v.y; s.z += v.z; s.w += v.w;
        s2.x += v.x * v.x; s2.y += v.y * v.y; s2.z += v.z * v.z; s2.w += v.w * v.w;
    }
    *(float4*)&shs[ng][cg * 4] = s;
    *(float4*)&sh2[ng][cg * 4] = s2;
    __syncthreads();
    if (tid < 64) {
        float a = 0.f, b = 0.f;
#pragma unroll
        for (int g = 0; g < 16; ++g) { a += shs[g][tid]; b += sh2[g][tid]; }
        atomicAdd(&g_stats[tid], (double)a);
        atomicAdd(&g_stats[64 + tid], (double)b);
    }
}

// ---------------- kernel 4: BN stats finalize + residual + affine apply ----------
__global__ void __launch_bounds__(256) finalize(
    const float* __restrict__ node, const float* __restrict__ gamma,
    const float* __restrict__ beta, float* __restrict__ out)
{
    __shared__ float s_scale[64], s_shift[64];
    const int tid = threadIdx.x;
    if (tid < 64) {
        double invN = 1.0 / (double)N_NODES;
        double mean = g_stats[tid] * invN;
        double var = g_stats[64 + tid] * invN - mean * mean;
        if (var < 0.0) var = 0.0;
        float sc = (float)(rsqrt(var + 1e-5) * (double)gamma[tid]);
        s_scale[tid] = sc;
        s_shift[tid] = beta[tid] - (float)mean * sc;
    }
    __syncthreads();

    int idx = blockIdx.x * blockDim.x + tid;
    float4 m = ((const float4*)g_msg)[idx];
    float4 x = ((const float4*)node)[idx];
    int f0 = (idx * 4) & 63;
    float4 r;
    r.x = x.x + m.x * s_scale[f0]     + s_shift[f0];
    r.y = x.y + m.y * s_scale[f0 + 1] + s_shift[f0 + 1];
    r.z = x.z + m.z * s_scale[f0 + 2] + s_shift[f0 + 2];
    r.w = x.w + m.w * s_scale[f0 + 3] + s_shift[f0 + 3];
    ((float4*)out)[idx] = r;
}

// ---------------- launch ----------------
extern "C" void kernel_launch(void* const* d_in, const int* in_sizes, int n_in,
                              void* d_out, int out_size) {
    const float* node  = (const float*)d_in[0];
    const void*  ei    = d_in[1];
    const float* ea    = (const float*)d_in[2];
    const float* Wf    = (const float*)d_in[3];
    const float* bf    = (const float*)d_in[4];
    const float* Ws    = (const float*)d_in[5];
    const float* bs    = (const float*)d_in[6];
    const float* gamma = (const float*)d_in[7];
    const float* beta  = (const float*)d_in[8];
    float* out = (float*)d_out;

    prep_B<<<1, 256>>>(Wf, Ws, (const unsigned int*)ei);          // 1
    node_gemm<<<(N_NODES + 63) / 64, 256>>>(node, bf, bs);        // 2
    edge_fused<<<N_EDGES / 128, 256>>>(ea, ei);                   // 3
    bn_reduce<<<592, 256>>>();                                    // 4
    finalize<<<(N_NODES * 64) / 1024, 256>>>(node, gamma, beta, out);  // 5
}